// round 17
// baseline (speedup 1.0000x reference)
#include <cuda_runtime.h>
#include <cuda_bf16.h>
#include <math.h>
#include <cstdint>

#define BB 8
#define CC 128
#define HH 96
#define WW 96
#define HO 48
#define WO 48
#define NN 2304   // HO*WO

typedef unsigned long long u64;

// ---- mma.sync helpers ----
__device__ __forceinline__ uint32_t smem_u32(const void* p) {
    uint32_t a;
    asm("{ .reg .u64 t; cvta.to.shared.u64 t, %1; cvt.u32.u64 %0, t; }" : "=r"(a) : "l"(p));
    return a;
}
__device__ __forceinline__ void ldm_x4(uint32_t& r0, uint32_t& r1, uint32_t& r2, uint32_t& r3, uint32_t addr) {
    asm volatile("ldmatrix.sync.aligned.m8n8.x4.shared.b16 {%0,%1,%2,%3}, [%4];"
                 : "=r"(r0), "=r"(r1), "=r"(r2), "=r"(r3) : "r"(addr));
}
__device__ __forceinline__ void ldm_x4_t(uint32_t& r0, uint32_t& r1, uint32_t& r2, uint32_t& r3, uint32_t addr) {
    asm volatile("ldmatrix.sync.aligned.m8n8.x4.trans.shared.b16 {%0,%1,%2,%3}, [%4];"
                 : "=r"(r0), "=r"(r1), "=r"(r2), "=r"(r3) : "r"(addr));
}
__device__ __forceinline__ void mma16816(float* d, const uint32_t* a, uint32_t b0, uint32_t b1) {
    asm volatile("mma.sync.aligned.m16n8k16.row.col.f32.bf16.bf16.f32 "
                 "{%0,%1,%2,%3}, {%4,%5,%6,%7}, {%8,%9}, {%0,%1,%2,%3};"
                 : "+f"(d[0]), "+f"(d[1]), "+f"(d[2]), "+f"(d[3])
                 : "r"(a[0]), "r"(a[1]), "r"(a[2]), "r"(a[3]), "r"(b0), "r"(b1));
}

// ---- cp.async helpers ----
__device__ __forceinline__ void cp16(uint32_t dst, const void* src) {
    asm volatile("cp.async.cg.shared.global [%0], [%1], 16;" :: "r"(dst), "l"(src));
}
__device__ __forceinline__ void cp16p(uint32_t dst, const void* src, uint32_t sz) {
    asm volatile("cp.async.cg.shared.global [%0], [%1], 16, %2;" :: "r"(dst), "l"(src), "r"(sz));
}
#define CP_COMMIT asm volatile("cp.async.commit_group;" ::: "memory")
#define CP_WAIT0  asm volatile("cp.async.wait_group 0;" ::: "memory")

// ---- mbarrier + bulk copy helpers ----
__device__ __forceinline__ void mbar_init(uint32_t mbar, uint32_t cnt) {
    asm volatile("mbarrier.init.shared.b64 [%0], %1;" :: "r"(mbar), "r"(cnt) : "memory");
}
__device__ __forceinline__ void mbar_expect_tx(uint32_t mbar, uint32_t bytes) {
    asm volatile("mbarrier.arrive.expect_tx.shared.b64 _, [%0], %1;" :: "r"(mbar), "r"(bytes) : "memory");
}
__device__ __forceinline__ void bulk_g2s(uint32_t dst, const void* src, uint32_t bytes, uint32_t mbar) {
    asm volatile("cp.async.bulk.shared::cluster.global.mbarrier::complete_tx::bytes [%0], [%1], %2, [%3];"
                 :: "r"(dst), "l"(src), "r"(bytes), "r"(mbar) : "memory");
}
__device__ __forceinline__ void mbar_wait(uint32_t mbar, uint32_t parity) {
    uint32_t done;
    asm volatile(
        "{\n\t.reg .pred p;\n\t"
        "mbarrier.try_wait.parity.acquire.cta.shared::cta.b64 p, [%1], %2;\n\t"
        "selp.b32 %0, 1, 0, p;\n\t}"
        : "=r"(done) : "r"(mbar), "r"(parity) : "memory");
    if (!done) {
        asm volatile(
            "{\n\t.reg .pred P1;\n\t"
            "WL_%=:\n\t"
            "mbarrier.try_wait.parity.acquire.cta.shared::cta.b64 P1, [%0], %1, 0x989680;\n\t"
            "@P1 bra.uni WD_%=;\n\t"
            "bra.uni WL_%=;\n\t"
            "WD_%=:\n\t}"
            :: "r"(mbar), "r"(parity) : "memory");
    }
}

// ---- bf16 hi/lo split store helpers ----
__device__ __forceinline__ void split2_store(__nv_bfloat16* ph, __nv_bfloat16* pl, float a, float b) {
    __nv_bfloat16 ha = __float2bfloat16(a), hb = __float2bfloat16(b);
    __nv_bfloat16 la = __float2bfloat16(a - __bfloat162float(ha));
    __nv_bfloat16 lb = __float2bfloat16(b - __bfloat162float(hb));
    *(__nv_bfloat162*)ph = __halves2bfloat162(ha, hb);
    *(__nv_bfloat162*)pl = __halves2bfloat162(la, lb);
}
__device__ __forceinline__ void split4_store(__nv_bfloat16* ph, __nv_bfloat16* pl, float4 v) {
    __nv_bfloat16 h0 = __float2bfloat16(v.x), h1 = __float2bfloat16(v.y);
    __nv_bfloat16 h2 = __float2bfloat16(v.z), h3 = __float2bfloat16(v.w);
    __nv_bfloat16 l0 = __float2bfloat16(v.x - __bfloat162float(h0));
    __nv_bfloat16 l1 = __float2bfloat16(v.y - __bfloat162float(h1));
    __nv_bfloat16 l2 = __float2bfloat16(v.z - __bfloat162float(h2));
    __nv_bfloat16 l3 = __float2bfloat16(v.w - __bfloat162float(h3));
    uint2 uh, ul;
    uh.x = ((uint32_t)__bfloat16_as_ushort(h1) << 16) | __bfloat16_as_ushort(h0);
    uh.y = ((uint32_t)__bfloat16_as_ushort(h3) << 16) | __bfloat16_as_ushort(h2);
    ul.x = ((uint32_t)__bfloat16_as_ushort(l1) << 16) | __bfloat16_as_ushort(l0);
    ul.y = ((uint32_t)__bfloat16_as_ushort(l3) << 16) | __bfloat16_as_ushort(l2);
    *(uint2*)ph = uh;
    *(uint2*)pl = ul;
}

#define SWZ(off) ((off) ^ (((off) >> 3) & 0x70))

// ---------------- scratch ----------------
__device__ __nv_bfloat16 g_fh[(size_t)BB*NN*CC];
__device__ __nv_bfloat16 g_fl[(size_t)BB*NN*CC];
__device__ __nv_bfloat16 g_gh[(size_t)BB*NN*CC];
__device__ __nv_bfloat16 g_gl[(size_t)BB*NN*CC];
__device__ __nv_bfloat16 g_hh[(size_t)BB*CC*NN];
__device__ __nv_bfloat16 g_hl[(size_t)BB*CC*NN];
__device__ float g_s[BB*CC*NN];
__device__ float g_attn[(size_t)BB*NN*NN];
__device__ __nv_bfloat16 g_ah[(size_t)BB*NN*NN];
__device__ __nv_bfloat16 g_al[(size_t)BB*NN*NN];
__device__ __nv_bfloat16 g_act_h[(size_t)BB*3*HH*WW*CC];
__device__ __nv_bfloat16 g_act_l[(size_t)BB*3*HH*WW*CC];
// weights: [br][ch=8][half][oc=128][k=152 (144 used, k = tap*16+i)]
__device__ __nv_bfloat16 g_wb2[3*8*2*128*152];
__device__ int g_work;
__device__ float g_pool[BB*2*CC];
__device__ float g_se[BB*CC];
__device__ float g_scale[3*CC];
__device__ float g_shift[3*CC];

// ---------------- BN fold (+ work counter reset) ----------------
__global__ void bn_prep(const float* fw, const float* fb, const float* fm, const float* fv,
                        const float* gw, const float* gb, const float* gm, const float* gv,
                        const float* hw, const float* hb, const float* hm, const float* hv) {
    int i = threadIdx.x;
    if (i == 0) g_work = 0;
    if (i >= 3*CC) return;
    int br = i / CC, c = i - br*CC;
    const float *w, *b, *m, *v;
    if (br == 0)      { w = fw; b = fb; m = fm; v = fv; }
    else if (br == 1) { w = gw; b = gb; m = gm; v = gv; }
    else              { w = hw; b = hb; m = hm; v = hv; }
    float inv = w[c] * rsqrtf(v[c] + 1e-5f);
    g_scale[i] = inv;
    g_shift[i] = b[c] - m[c]*inv;
}

// ---------------- weight prep ----------------
__global__ __launch_bounds__(256) void wprep(const float* __restrict__ wf,
                                             const float* __restrict__ wg,
                                             const float* __restrict__ wh)
{
    int idx = blockIdx.x * 256 + threadIdx.x;     // 3*8*2*128*152 = 933888
    if (idx >= 3*8*2*128*152) return;
    int br = idx / (8*2*128*152);
    int r  = idx - br*(8*2*128*152);
    int ch = r / (2*128*152);
    int r2 = r - ch*(2*128*152);
    int half = r2 / (128*152);
    int r3 = r2 - half*(128*152);
    int oc = r3 / 152;
    int kk = r3 - oc*152;
    if (kk >= 144) { g_wb2[idx] = __float2bfloat16(0.f); return; }
    int t = kk >> 4, i = kk & 15;
    int ic = ch*16 + i;
    const float* w = (br == 0) ? wf : (br == 1) ? wg : wh;
    float v = w[((size_t)oc*CC + ic)*9 + t];
    __nv_bfloat16 h = __float2bfloat16(v);
    g_wb2[idx] = half ? __float2bfloat16(v - __bfloat162float(h)) : h;
}

// ---------------- activation prep ----------------
__global__ __launch_bounds__(256) void act_prep(const float* __restrict__ x)
{
    __shared__ float xs[128][97];
    int iy = blockIdx.x, b = blockIdx.y;
    int tid = threadIdx.x;

    #pragma unroll
    for (int it = 0; it < 12; it++) {
        int idx = it*256 + tid;
        int c = idx / 24, q = idx - (idx/24)*24;
        float4 v = *(const float4*)&x[((size_t)(b*CC + c)*HH + iy)*WW + q*4];
        xs[c][q*4 + 0] = v.x; xs[c][q*4 + 1] = v.y;
        xs[c][q*4 + 2] = v.z; xs[c][q*4 + 3] = v.w;
    }
    __syncthreads();

    #pragma unroll 1
    for (int br = 0; br < 3; br++) {
        __nv_bfloat16* ah = g_act_h + ((size_t)(b*3 + br)*HH*WW + (size_t)iy*WW)*CC;
        __nv_bfloat16* al = g_act_l + ((size_t)(b*3 + br)*HH*WW + (size_t)iy*WW)*CC;
        #pragma unroll
        for (int it = 0; it < 24; it++) {
            int idx = it*256 + tid;
            int ix = idx >> 6, icp = idx & 63;
            int ic = icp*2;
            float sc0 = g_scale[br*CC + ic],     sh0 = g_shift[br*CC + ic];
            float sc1 = g_scale[br*CC + ic + 1], sh1 = g_shift[br*CC + ic + 1];
            float v0 = fmaxf(fmaf(xs[ic][ix],     sc0, sh0), 0.f);
            float v1 = fmaxf(fmaf(xs[ic + 1][ix], sc1, sh1), 0.f);
            size_t off = (size_t)ix*CC + ic;
            split2_store(ah + off, al + off, v0, v1);
        }
    }
}

// ---------------- conv3x3 s2: persistent halo-staged implicit GEMM ----------------
// chunk = 16 ic x 9 taps (k=144, padded 152). Buffer: A 77824 | haloH 18432 | haloL 18432
#define CV_ABYTES 77824
#define CV_HOFF   77824
#define CV_HSZ    18432
#define CV_BUFB   114688
#define CV_SMEM_BYTES (2*CV_BUFB)   // 229376 -> 1 CTA/SM
#define CV_NTILES (18*3*BB)         // 432

__device__ __forceinline__ void cv_stage(uint32_t boff, uint32_t mbar, int tid, int ch,
    int oy0, int ox0, const __nv_bfloat16* wsrc,
    const __nv_bfloat16* acth, const __nv_bfloat16* actl)
{
    if (tid == 0) {
        mbar_expect_tx(mbar, CV_ABYTES);
        bulk_g2s(boff, wsrc + (size_t)ch*(2*128*152), CV_ABYTES, mbar);
    }
    // halo: 17 iy x 33 ix pixels, 16 ic (32B) x hi/lo; 2244 cp16 ops
    int IY0 = 2*oy0 - 1, IX0 = 2*ox0 - 1;
    #pragma unroll
    for (int it = 0; it < 9; it++) {
        int idx = it*256 + tid;           // 0..2303
        if (idx < 2244) {
            int pix = idx >> 2, q = idx & 3;
            int half = q >> 1, sub = q & 1;
            int iyl = pix / 33, ixl = pix - iyl*33;
            int iy = IY0 + iyl, ix = IX0 + ixl;
            bool ok = ((unsigned)iy < HH) && ((unsigned)ix < WW);
            const __nv_bfloat16* src = (half ? actl : acth)
                + (ok ? ((size_t)(iy*WW + ix))*CC + ch*16 + sub*8 : 0);
            uint32_t doff = (uint32_t)(pix*32 + sub*16);
            doff = SWZ(doff);
            cp16p(boff + (uint32_t)(CV_HOFF + half*CV_HSZ) + doff, src, ok ? 16u : 0u);
        }
    }
    CP_COMMIT;
}

__global__ __launch_bounds__(256, 1) void conv_hmma(
    const float* __restrict__ bf, const float* __restrict__ bg, const float* __restrict__ bh)
{
    extern __shared__ __nv_bfloat16 sm[];
    __shared__ u64 mbars[2];
    __shared__ int s_tile;
    int tid = threadIdx.x, wid = tid >> 5, lane = tid & 31;

    uint32_t sbase = smem_u32(sm);
    uint32_t mb0 = smem_u32(&mbars[0]);
    uint32_t mb1 = smem_u32(&mbars[1]);
    int wr = wid >> 2, wc = wid & 3;
    int arow = wr*64 + (lane & 15);
    int khalf16 = (lane >> 4) * 16;    // byte offset of 8-elem k half
    int blane = (lane & 15);
    int r4 = lane >> 2, c2 = (lane & 3) * 2;

    if (tid == 0) {
        mbar_init(mb0, 1);
        mbar_init(mb1, 1);
        asm volatile("fence.proxy.async;" ::: "memory");
    }
    __syncthreads();

    int p0 = 0, p1 = 0;

    #pragma unroll 1
    while (true) {
        if (tid == 0) s_tile = atomicAdd(&g_work, 1);
        __syncthreads();
        int wk = s_tile;
        if (wk >= CV_NTILES) break;

        int b = wk / 54;
        int r = wk - b*54;
        int br = r / 18;
        int tIdx = r - br*18;
        int oy0 = (tIdx/3)*8, ox0 = (tIdx - (tIdx/3)*3)*16;

        const float* bias = (br == 0) ? bf : (br == 1) ? bg : bh;
        const __nv_bfloat16* acth = g_act_h + (size_t)(b*3 + br)*HH*WW*CC;
        const __nv_bfloat16* actl = g_act_l + (size_t)(b*3 + br)*HH*WW*CC;
        const __nv_bfloat16* wsrc = g_wb2 + (size_t)br*8*2*128*152;

        float acc[4][4][4];
        #pragma unroll
        for (int mt = 0; mt < 4; mt++)
            #pragma unroll
            for (int nt = 0; nt < 4; nt++)
                #pragma unroll
                for (int q = 0; q < 4; q++) acc[mt][nt][q] = 0.f;

        cv_stage(sbase, mb0, tid, 0, oy0, ox0, wsrc, acth, actl);

        #pragma unroll 1
        for (int ch = 0; ch < 8; ch++) {
            int cur = ch & 1;
            if (cur) { mbar_wait(mb1, p1); p1 ^= 1; }
            else     { mbar_wait(mb0, p0); p0 ^= 1; }
            CP_WAIT0;
            __syncthreads();
            if (ch + 1 < 8) {
                cv_stage(sbase + (uint32_t)((cur ^ 1)*CV_BUFB), cur ? mb0 : mb1, tid, ch + 1,
                         oy0, ox0, wsrc, acth, actl);
            }
            uint32_t cb = sbase + (uint32_t)(cur*CV_BUFB);

            #pragma unroll
            for (int kb = 0; kb < 9; kb++) {
                int tty = kb / 3, ttx = kb - tty*3;
                uint32_t afr[2][4][4];
                #pragma unroll
                for (int s = 0; s < 2; s++)
                    #pragma unroll
                    for (int mt = 0; mt < 4; mt++) {
                        int row = arow + mt*16;
                        uint32_t addr = cb + (uint32_t)((s*128 + row)*304 + kb*32 + khalf16);
                        ldm_x4(afr[s][mt][0], afr[s][mt][1], afr[s][mt][2], afr[s][mt][3], addr);
                    }
                uint32_t bfr[2][2][4];
                #pragma unroll
                for (int s = 0; s < 2; s++)
                    #pragma unroll
                    for (int t2 = 0; t2 < 2; t2++) {
                        int iyl = 2*(wc*2 + t2) + tty;
                        int ixl = 2*blane + ttx;
                        uint32_t off = (uint32_t)((iyl*33 + ixl)*32 + khalf16);
                        off = SWZ(off);
                        uint32_t addr = cb + (uint32_t)(CV_HOFF + s*CV_HSZ) + off;
                        ldm_x4(bfr[s][t2][0], bfr[s][t2][1], bfr[s][t2][2], bfr[s][t2][3], addr);
                    }
                #pragma unroll
                for (int pi = 0; pi < 3; pi++) {
                    int fs = (pi == 2) ? 1 : 0;
                    int gs = (pi == 1) ? 1 : 0;
                    #pragma unroll
                    for (int mt = 0; mt < 4; mt++)
                        #pragma unroll
                        for (int nt = 0; nt < 4; nt++) {
                            int t2 = nt >> 1, hl = nt & 1;
                            mma16816(acc[mt][nt], afr[fs][mt], bfr[gs][t2][hl], bfr[gs][t2][2 + hl]);
                        }
                }
            }
        }

        // epilogue
        if (br < 2) {
            __nv_bfloat16* ghi = (br == 0) ? g_fh : g_gh;
            __nv_bfloat16* glo = (br == 0) ? g_fl : g_gl;
            #pragma unroll
            for (int mt = 0; mt < 4; mt++) {
                int ocA = wr*64 + mt*16 + r4;
                float bvA = bias[ocA], bvB = bias[ocA + 8];
                #pragma unroll
                for (int nt = 0; nt < 4; nt++) {
                    int nloc = wc*32 + nt*8 + c2;
                    int nglob = (oy0 + (nloc >> 4))*WO + ox0 + (nloc & 15);
                    size_t o0 = ((size_t)(b*NN + nglob))*CC;
                    size_t o1 = o0 + CC;
                    float vA0 = acc[mt][nt][0] + bvA, vA1 = acc[mt][nt][1] + bvA;
                    float vB0 = acc[mt][nt][2] + bvB, vB1 = acc[mt][nt][3] + bvB;
                    __nv_bfloat16 h;
                    h = __float2bfloat16(vA0); ghi[o0 + ocA] = h;
                    glo[o0 + ocA] = __float2bfloat16(vA0 - __bfloat162float(h));
                    h = __float2bfloat16(vA1); ghi[o1 + ocA] = h;
                    glo[o1 + ocA] = __float2bfloat16(vA1 - __bfloat162float(h));
                    h = __float2bfloat16(vB0); ghi[o0 + ocA + 8] = h;
                    glo[o0 + ocA + 8] = __float2bfloat16(vB0 - __bfloat162float(h));
                    h = __float2bfloat16(vB1); ghi[o1 + ocA + 8] = h;
                    glo[o1 + ocA + 8] = __float2bfloat16(vB1 - __bfloat162float(h));
                }
            }
        } else {
            #pragma unroll
            for (int mt = 0; mt < 4; mt++) {
                int ocA = wr*64 + mt*16 + r4;
                float bvA = bias[ocA], bvB = bias[ocA + 8];
                #pragma unroll
                for (int nt = 0; nt < 4; nt++) {
                    int nloc = wc*32 + nt*8 + c2;
                    int nglob = (oy0 + (nloc >> 4))*WO + ox0 + (nloc & 15);
                    size_t oA = ((size_t)(b*CC + ocA))*NN + nglob;
                    size_t oB = ((size_t)(b*CC + ocA + 8))*NN + nglob;
                    split2_store(g_hh + oA, g_hl + oA, acc[mt][nt][0] + bvA, acc[mt][nt][1] + bvA);
                    split2_store(g_hh + oB, g_hl + oB, acc[mt][nt][2] + bvB, acc[mt][nt][3] + bvB);
                }
            }
        }
    }
}

// ---------------- scores: 128x128 tile, 32-k chunks, double-buffered, 2 CTA/SM ----------------
#define SC_A (128*40)
#define SC_BUF (4*SC_A)
#define SC_SMEM_BYTES (2*SC_BUF*2)      // 81920

__device__ __forceinline__ void sc_stage(uint32_t boff, int tid, int b, int kc, int n0, int m0)
{
    #pragma unroll
    for (int it = 0; it < 8; it++) {
        int idx = it*256 + tid;
        int mat = idx >> 9;
        int r = idx & 511;
        int row = r >> 2, kq = (r & 3) * 8;
        const __nv_bfloat16* base = (mat == 0) ? g_fh : (mat == 1) ? g_fl : (mat == 2) ? g_gh : g_gl;
        int rbase = (mat < 2) ? n0 : m0;
        cp16(boff + (uint32_t)((mat*SC_A + row*40 + kq)*2),
             base + (size_t)(b*NN + rbase + row)*CC + kc*32 + kq);
    }
}

__global__ __launch_bounds__(256, 2) void scores_hmma()
{
    extern __shared__ __nv_bfloat16 sm[];
    int tid = threadIdx.x;
    int wid = tid >> 5, lane = tid & 31;
    int b  = blockIdx.z;
    int n0 = blockIdx.y * 128;
    int m0 = blockIdx.x * 128;

    uint32_t sbase = smem_u32(sm);
    int wr = wid >> 2;
    int wc = wid & 3;

    float acc[4][4][4];
    #pragma unroll
    for (int mt = 0; mt < 4; mt++)
        #pragma unroll
        for (int nt = 0; nt < 4; nt++)
            #pragma unroll
            for (int r = 0; r < 4; r++) acc[mt][nt][r] = 0.f;

    int arow = wr*64 + (lane & 15);
    int brow = wc*32 + (lane & 15);
    int chalf = (lane >> 4) * 8;

    sc_stage(sbase, tid, b, 0, n0, m0);
    CP_COMMIT;

    #pragma unroll 1
    for (int kc = 0; kc < 4; kc++) {
        int cur = kc & 1;
        CP_WAIT0;
        __syncthreads();
        if (kc + 1 < 4) {
            sc_stage(sbase + (uint32_t)((cur ^ 1)*SC_BUF*2), tid, b, kc + 1, n0, m0);
            CP_COMMIT;
        }
        uint32_t cb = sbase + (uint32_t)(cur*SC_BUF*2);

        #pragma unroll
        for (int ks = 0; ks < 2; ks++) {
            int kcol = ks*16 + chalf;
            uint32_t afr[2][4][4];
            #pragma unroll
            for (int s = 0; s < 2; s++)
                #pragma unroll
                for (int mt = 0; mt < 4; mt++) {
                    uint32_t addr = cb + (uint32_t)((s*SC_A + (arow + mt*16)*40 + kcol) * 2);
                    ldm_x4(afr[s][mt][0], afr[s][mt][1], afr[s][mt][2], afr[s][mt][3], addr);
                }
            uint32_t bfr[2][2][4];
            #pragma unroll
            for (int s = 0; s < 2; s++)
                #pragma unroll
                for (int t2 = 0; t2 < 2; t2++) {
                    uint32_t addr = cb + (uint32_t)(((2 + s)*SC_A + (brow + t2*16)*40 + kcol) * 2);
                    ldm_x4(bfr[s][t2][0], bfr[s][t2][1], bfr[s][t2][2], bfr[s][t2][3], addr);
                }
            #pragma unroll
            for (int pi = 0; pi < 3; pi++) {
                int fs = (pi == 2) ? 1 : 0;
                int gs = (pi == 1) ? 1 : 0;
                #pragma unroll
                for (int mt = 0; mt < 4; mt++)
                    #pragma unroll
                    for (int nt = 0; nt < 4; nt++) {
                        int t2 = nt >> 1, hl = nt & 1;
                        mma16816(acc[mt][nt], afr[fs][mt], bfr[gs][t2][hl], bfr[gs][t2][2 + hl]);
                    }
            }
        }
    }

    float* Sp = g_attn + (size_t)b*NN*NN;
    int r4 = lane >> 2, c2 = (lane & 3) * 2;
    #pragma unroll
    for (int mt = 0; mt < 4; mt++) {
        int row0 = n0 + wr*64 + mt*16 + r4;
        #pragma unroll
        for (int nt = 0; nt < 4; nt++) {
            int col = m0 + wc*32 + nt*8 + c2;
            *(float2*)&Sp[(size_t)row0*NN + col]       = make_float2(acc[mt][nt][0], acc[mt][nt][1]);
            *(float2*)&Sp[(size_t)(row0 + 8)*NN + col] = make_float2(acc[mt][nt][2], acc[mt][nt][3]);
        }
    }
}

// ---------------- softmax: fp32 in, bf16 hi/lo out ----------------
__global__ __launch_bounds__(288) void softmax_rows()
{
    __shared__ float red[9];
    const float4* p = (const float4*)(g_attn + (size_t)blockIdx.x * NN);
    int tid = threadIdx.x;
    int wid = tid >> 5, lane = tid & 31;

    float4 v0 = p[tid];
    float4 v1 = p[tid + 288];

    float mx = fmaxf(fmaxf(fmaxf(v0.x, v0.y), fmaxf(v0.z, v0.w)),
                     fmaxf(fmaxf(v1.x, v1.y), fmaxf(v1.z, v1.w)));
    #pragma unroll
    for (int o = 16; o > 0; o >>= 1) mx = fmaxf(mx, __shfl_xor_sync(0xffffffffu, mx, o));
    if (lane == 0) red[wid] = mx;
    __syncthreads();
    float m = red[0];
    #pragma unroll
    for (int i = 1; i < 9; i++) m = fmaxf(m, red[i]);
    __syncthreads();

    v0.x = __expf(v0.x - m); v0.y = __expf(v0.y - m);
    v0.z = __expf(v0.z - m); v0.w = __expf(v0.w - m);
    v1.x = __expf(v1.x - m); v1.y = __expf(v1.y - m);
    v1.z = __expf(v1.z - m); v1.w = __expf(v1.w - m);

    float sum = (v0.x + v0.y) + (v0.z + v0.w) + (v1.x + v1.y) + (v1.z + v1.w);
    #pragma unroll
    for (int o = 16; o > 0; o >>= 1) sum += __shfl_xor_sync(0xffffffffu, sum, o);
    if (lane == 0) red[wid] = sum;
    __syncthreads();
    float s = red[0];
    #pragma unroll
    for (int i = 1; i < 9; i++) s += red[i];
    float inv = 1.f / s;

    v0.x *= inv; v0.y *= inv; v0.z *= inv; v0.w *= inv;
    v1.x *= inv; v1.y *= inv; v1.z *= inv; v1.w *= inv;

    __nv_bfloat16* ah = g_ah + (size_t)blockIdx.x * NN;
    __nv_bfloat16* al = g_al + (size_t)blockIdx.x * NN;
    split4_store(ah + tid*4, al + tid*4, v0);
    split4_store(ah + (tid + 288)*4, al + (tid + 288)*4, v1);
}

// ---------------- s = gamma * (h @ attn), m-tile 64, double-buffered, 2 CTA/SM ----------------
#define SV_A (128*72)
#define SV_B (64*72)
#define SV_BUF (2*SV_A + 2*SV_B)
#define SV_SMEM_BYTES (2*SV_BUF*2)        // 110592 B

__device__ __forceinline__ void sv_stage(uint32_t boff, int tid, int k0, int m0,
    const __nv_bfloat16* Ah, const __nv_bfloat16* Al,
    const __nv_bfloat16* Bh, const __nv_bfloat16* Bl)
{
    #pragma unroll
    for (int it = 0; it < 8; it++) {
        int idx = it*256 + tid;
        int half = (idx >= 1024);
        int r = idx - half*1024;
        int c = r >> 3, kq = (r & 7) * 8;
        cp16(boff + (uint32_t)((half*SV_A + c*72 + kq)*2),
             (half ? Al : Ah) + (size_t)c*NN + k0 + kq);
    }
    #pragma unroll
    for (int it = 0; it < 4; it++) {
        int idx = it*256 + tid;
        int half = (idx >= 512);
        int r = idx - half*512;
        int kr = r >> 3, mq = (r & 7) * 8;
        cp16(boff + (uint32_t)((2*SV_A + half*SV_B + kr*72 + mq)*2),
             (half ? Bl : Bh) + (size_t)(k0 + kr)*NN + m0 + mq);
    }
}

__global__ __launch_bounds__(256, 2) void sv_hmma(const float* __restrict__ gamma)
{
    extern __shared__ __nv_bfloat16 sm[];
    int tid = threadIdx.x;
    int wid = tid >> 5, lane = tid & 31;
    int b  = blockIdx.z;
    int m0 = blockIdx.x * 64;

    const __nv_bfloat16* Ah = g_hh + (size_t)b*CC*NN;
    const __nv_bfloat16* Al = g_hl + (size_t)b*CC*NN;
    const __nv_bfloat16* Bh = g_ah + (size_t)b*NN*NN;
    const __nv_bfloat16* Bl = g_al + (size_t)b*NN*NN;

    int wr = wid >> 2;
    int wc = wid & 3;

    float acc[4][2][4];
    #pragma unroll
    for (int mt = 0; mt < 4; mt++)
        #pragma unroll
        for (int nt = 0; nt < 2; nt++)
            #pragma unroll
            for (int r = 0; r < 4; r++) acc[mt][nt][r] = 0.f;

    uint32_t sbase = smem_u32(sm);
    int arow = wr*64 + (lane & 15);
    int chalf = (lane >> 4) * 8;

    sv_stage(sbase, tid, 0, m0, Ah, Al, Bh, Bl);
    CP_COMMIT;

    #pragma unroll 1
    for (int kc = 0; kc < 36; kc++) {
        int cur = kc & 1;
        CP_WAIT0;
        __syncthreads();
        if (kc + 1 < 36) {
            sv_stage(sbase + (uint32_t)((cur ^ 1)*SV_BUF*2), tid, (kc + 1)*64, m0, Ah, Al, Bh, Bl);
            CP_COMMIT;
        }
        uint32_t cb = sbase + (uint32_t)(cur*SV_BUF*2);

        #pragma unroll
        for (int ks = 0; ks < 4; ks++) {
            uint32_t afr[2][4][4];
            #pragma unroll
            for (int s = 0; s < 2; s++)
                #pragma unroll
                for (int mt = 0; mt < 4; mt++) {
                    uint32_t addr = cb + (uint32_t)((s*SV_A + (arow + mt*16)*72 + ks*16 + chalf) * 2);
                    ldm_x4(afr[s][mt][0], afr[s][mt][1], afr[s][mt][2], afr[s][mt][3], addr);
                }
            uint32_t bfr[2][4];
            #pragma unroll
            for (int s = 0; s < 2; s++) {
                uint32_t addr = cb + (uint32_t)((2*SV_A + s*SV_B + (ks*16 + (lane & 15))*72
                                                + wc*16 + chalf) * 2);
                ldm_x4_t(bfr[s][0], bfr[s][1], bfr[s][2], bfr[s][3], addr);
            }
            #pragma unroll
            for (int pi = 0; pi < 3; pi++) {
                int fs = (pi == 2) ? 1 : 0;
                int gs = (pi == 1) ? 1 : 0;
                #pragma unroll
                for (int mt = 0; mt < 4; mt++)
                    #pragma unroll
                    for (int nt = 0; nt < 2; nt++)
                        mma16816(acc[mt][nt], afr[fs][mt], bfr[gs][2*nt], bfr[gs][2*nt + 1]);
            }
        }
    }

    float gm = gamma[0];
    int r4 = lane >> 2, c2 = (lane & 3) * 2;
    #pragma unroll
    for (int mt = 0; mt < 4; mt++) {
        int row0 = wr*64 + mt*16 + r4;
        #pragma unroll
        for (int nt = 0; nt < 2; nt++) {
            int col = m0 + wc*16 + nt*8 + c2;
            *(float2*)&g_s[(size_t)(b*CC + row0)*NN + col] =
                make_float2(gm*acc[mt][nt][0], gm*acc[mt][nt][1]);
            *(float2*)&g_s[(size_t)(b*CC + row0 + 8)*NN + col] =
                make_float2(gm*acc[mt][nt][2], gm*acc[mt][nt][3]);
        }
    }
}

// ---------------- global means of x and s ----------------
__global__ __launch_bounds__(256) void pool_means(const float* __restrict__ x)
{
    __shared__ float red[256];
    int idx = blockIdx.x;
    const float* p; int n; float* o;
    if (idx < BB*CC) {
        int b = idx >> 7, c = idx & 127;
        p = x + (b*CC + c)*HH*WW; n = HH*WW; o = &g_pool[b*2*CC + c];
    } else {
        int k = idx - BB*CC;
        int b = k >> 7, c = k & 127;
        p = g_s + (b*CC + c)*NN; n = NN; o = &g_pool[b*2*CC + CC + c];
    }
    int tid = threadIdx.x;
    float s = 0.f;
    for (int i = tid; i < n; i += 256) s += p[i];
    red[tid] = s; __syncthreads();
    for (int st = 128; st > 0; st >>= 1) { if (tid < st) red[tid] += red[tid + st]; __syncthreads(); }
    if (tid == 0) *o = red[0] / (float)n;
}

// ---------------- SE MLP ----------------
__global__ __launch_bounds__(256) void se_mlp(const float* __restrict__ cw, const float* __restrict__ cb,
                                              const float* __restrict__ uw, const float* __restrict__ ub)
{
    __shared__ float hid[BB*42];
    int tid = threadIdx.x;
    for (int t = tid; t < BB*42; t += 256) {
        int b = t / 42, j = t - b*42;
        const float* pr = &g_pool[b*2*CC];
        const float* wr = &cw[j*2*CC];
        float s = cb[j];
        for (int k = 0; k < 2*CC; k++) s = fmaf(fmaxf(pr[k], 0.f), wr[k], s);
        hid[t] = fmaxf(s, 0.f);
    }
    __syncthreads();
    for (int t = tid; t < BB*CC; t += 256) {
        int b = t >> 7, o = t & 127;
        float s = ub[o];
        const float* hr = &hid[b*42];
        const float* wr = &uw[o*42];
        for (int j = 0; j < 42; j++) s = fmaf(hr[j], wr[j], s);
        g_se[t] = s;
    }
}

// ---------------- epilogue ----------------
__global__ __launch_bounds__(256) void final_out(const float* __restrict__ x, float* __restrict__ out)
{
    int id = blockIdx.x * 256 + threadIdx.x;
    if (id >= BB*CC*NN) return;
    int ox = id % WO; int t = id / WO;
    int oy = t % HO;  t /= HO;
    int c  = t % CC;  int b = t / CC;
    const float* xp = x + ((b*CC + c)*HH + 2*oy)*WW + 2*ox;
    float left = 0.25f * (xp[0] + xp[1] + xp[WW] + xp[WW + 1]);
    float sv = g_s[id];
    float se = g_se[b*CC + c];
    out[id] = (left + sv) * (1.f + se);
}

// ---------------- launch ----------------
extern "C" void kernel_launch(void* const* d_in, const int* in_sizes, int n_in,
                              void* d_out, int out_size)
{
    const float* x    = (const float*)d_in[0];
    const float* fbw  = (const float*)d_in[1];
    const float* fbb  = (const float*)d_in[2];
    const float* fbm  = (const float*)d_in[3];
    const float* fbv  = (const float*)d_in[4];
    const float* f_w  = (const float*)d_in[5];
    const float* f_b  = (const float*)d_in[6];
    const float* gbw  = (const float*)d_in[7];
    const float* gbb  = (const float*)d_in[8];
    const float* gbm  = (const float*)d_in[9];
    const float* gbv  = (const float*)d_in[10];
    const float* g_w  = (const float*)d_in[11];
    const float* g_b  = (const float*)d_in[12];
    const float* hbw  = (const float*)d_in[13];
    const float* hbb  = (const float*)d_in[14];
    const float* hbm  = (const float*)d_in[15];
    const float* hbv  = (const float*)d_in[16];
    const float* h_w  = (const float*)d_in[17];
    const float* h_b  = (const float*)d_in[18];
    const float* se_cw = (const float*)d_in[19];
    const float* se_cb = (const float*)d_in[20];
    const float* se_uw = (const float*)d_in[21];
    const float* se_ub = (const float*)d_in[22];
    const float* gamma = (const float*)d_in[23];
    float* out = (float*)d_out;

    static int smem_set = 0;
    if (!smem_set) {
        cudaFuncSetAttribute(scores_hmma, cudaFuncAttributeMaxDynamicSharedMemorySize, SC_SMEM_BYTES);
        cudaFuncSetAttribute(sv_hmma,     cudaFuncAttributeMaxDynamicSharedMemorySize, SV_SMEM_BYTES);
        cudaFuncSetAttribute(conv_hmma,   cudaFuncAttributeMaxDynamicSharedMemorySize, CV_SMEM_BYTES);
        smem_set = 1;
    }

    bn_prep<<<1, 384>>>(fbw, fbb, fbm, fbv, gbw, gbb, gbm, gbv, hbw, hbb, hbm, hbv);
    wprep<<<(3*8*2*128*152 + 255)/256, 256>>>(f_w, g_w, h_w);
    act_prep<<<dim3(HH, BB), 256>>>(x);

    conv_hmma<<<148, 256, CV_SMEM_BYTES>>>(f_b, g_b, h_b);

    scores_hmma<<<dim3(18, 18, BB), 256, SC_SMEM_BYTES>>>();
    softmax_rows<<<BB*NN, 288>>>();
    sv_hmma<<<dim3(36, 1, BB), 256, SV_SMEM_BYTES>>>(gamma);

    pool_means<<<2*BB*CC, 256>>>(x);
    se_mlp<<<1, 256>>>(se_cw, se_cb, se_uw, se_ub);

    final_out<<<(BB*CC*NN + 255)/256, 256>>>(x, out);
}